// round 4
// baseline (speedup 1.0000x reference)
#include <cuda_runtime.h>
#include <math.h>

static constexpr int BATCH  = 16;
static constexpr int C      = 128;
static constexpr int N      = 16384;     // H*W
static constexpr int SPLITK = 16;
static constexpr int CHUNK  = N / SPLITK;    // 1024
static constexpr int NTILES = N / 128;       // 128
static constexpr size_t OUT_ELEMS = (size_t)BATCH * C * N;   // 33,554,432

// ---------------- scratch (static device globals; no allocations) ----------
__device__ float g_kg  [(size_t)BATCH * C * N];              // k * sigmoid(input_gate)
__device__ float g_v   [(size_t)BATCH * C * N];              // v projection
__device__ float g_part[(size_t)BATCH * SPLITK * C * C];     // split-K knowledge partials
__device__ float g_fsum[(size_t)BATCH * C * NTILES];         // forget-gate partial sums
__device__ float g_E   [(size_t)BATCH * C * C];              // E = Wp * M^T
__device__ float g_F   [(size_t)BATCH * C * C];              // F = E * Wq
__device__ float g_fb  [(size_t)BATCH * C];                  // fb = E*bq + bp

__device__ __forceinline__ float sigmoidf_(float v) {
    return 1.0f / (1.0f + __expf(-v));
}

// 8x8 register-tile micro-kernel over one 8-deep smem K-slab.
__device__ __forceinline__ void mm8(float (&acc)[8][8],
                                    const float (&As)[8][128],
                                    const float (&Bs)[8][128],
                                    int ty, int tx)
{
#pragma unroll
    for (int k = 0; k < 8; k++) {
        float a_[8], b_[8];
#pragma unroll
        for (int i = 0; i < 8; i++) a_[i] = As[k][ty * 8 + i];
#pragma unroll
        for (int j = 0; j < 8; j++) b_[j] = Bs[k][tx * 8 + j];
#pragma unroll
        for (int i = 0; i < 8; i++)
#pragma unroll
            for (int j = 0; j < 8; j++)
                acc[i][j] = fmaf(a_[i], b_[j], acc[i][j]);
    }
}

// ---------------------------------------------------------------------------
// Kernel 1: fused projections.
//   type 0: rows interleave (k, input_gate) per channel -> kg = (k+bk)*sig(g2+bg2)
//   type 1: rows interleave (v, forget_gate)            -> v stored, sum sig(g1)
// Per block: 128 virtual M rows (64 channels x 2), 128 N columns, K = C = 128.
// ---------------------------------------------------------------------------
__global__ void __launch_bounds__(256, 2)
proj_kernel(const float* __restrict__ x,
            const float* __restrict__ Wk, const float* __restrict__ bk,
            const float* __restrict__ Wv, const float* __restrict__ bv,
            const float* __restrict__ Wg, const float* __restrict__ bg)
{
    __shared__ float As[8][128];
    __shared__ float Bs[8][128];
    __shared__ float red[64][16];

    const int type  = blockIdx.z & 1;
    const int b     = blockIdx.z >> 1;
    const int cbase = blockIdx.y << 6;   // 0 or 64
    const int n0    = blockIdx.x << 7;

    const float *W1, *W2, *b1, *b2;
    if (type == 0) { W1 = Wk; b1 = bk; W2 = Wg + C * C; b2 = bg + C; } // k / input gate
    else           { W1 = Wv; b1 = bv; W2 = Wg;         b2 = bg;     } // v / forget gate

    const int tid = threadIdx.x;
    const int tx = tid & 15, ty = tid >> 4;

    // A loader: virtual row am = 2*cc + p  (p=0 -> W1 row, p=1 -> W2 row)
    const int am = tid >> 1;
    const int ak = (tid & 1) << 2;
    const float* Wrow = ((am & 1) ? W2 : W1) + (size_t)(cbase + (am >> 1)) * C + ak;

    // B loader: X tile, coalesced along n
    const int bkr = tid >> 5;
    const int bn  = (tid & 31) << 2;
    const float* Xb = x + (size_t)b * C * N + (size_t)bkr * N + n0 + bn;

    float acc[8][8] = {};
#pragma unroll 1
    for (int kk = 0; kk < C; kk += 8) {
        float4 wa = *(const float4*)(Wrow + kk);
        As[ak + 0][am] = wa.x; As[ak + 1][am] = wa.y;
        As[ak + 2][am] = wa.z; As[ak + 3][am] = wa.w;
        *(float4*)&Bs[bkr][bn] = *(const float4*)(Xb + (size_t)kk * N);
        __syncthreads();
        mm8(acc, As, Bs, ty, tx);
        __syncthreads();
    }

    const int ncol = n0 + tx * 8;

    if (type == 0) {
#pragma unroll
        for (int p = 0; p < 4; p++) {
            const int c = cbase + ty * 4 + p;
            const float bb1 = b1[c], bb2 = b2[c];
            float o[8];
#pragma unroll
            for (int j = 0; j < 8; j++) {
                float kv = acc[2 * p][j]     + bb1;
                float gv = acc[2 * p + 1][j] + bb2;
                o[j] = kv * sigmoidf_(gv);
            }
            float* dst = g_kg + ((size_t)b * C + c) * N + ncol;
            *(float4*)(dst)     = make_float4(o[0], o[1], o[2], o[3]);
            *(float4*)(dst + 4) = make_float4(o[4], o[5], o[6], o[7]);
        }
    } else {
#pragma unroll
        for (int p = 0; p < 4; p++) {
            const int cc = ty * 4 + p;
            const int c  = cbase + cc;
            const float bb1 = b1[c], bb2 = b2[c];
            float o[8]; float s = 0.f;
#pragma unroll
            for (int j = 0; j < 8; j++) {
                o[j] = acc[2 * p][j] + bb1;
                s += sigmoidf_(acc[2 * p + 1][j] + bb2);
            }
            float* dst = g_v + ((size_t)b * C + c) * N + ncol;
            *(float4*)(dst)     = make_float4(o[0], o[1], o[2], o[3]);
            *(float4*)(dst + 4) = make_float4(o[4], o[5], o[6], o[7]);
            red[cc][tx] = s;
        }
        __syncthreads();
        if (tid < 64) {
            float s = 0.f;
#pragma unroll
            for (int t = 0; t < 16; t++) s += red[tid][t];
            g_fsum[((size_t)b * C + cbase + tid) * NTILES + blockIdx.x] = s;
        }
    }
}

// ---------------------------------------------------------------------------
// Kernel 2: knowledge partials.  part[b][s][c][d] = sum_{n in chunk s} kg[c,n]*v[d,n]
// ---------------------------------------------------------------------------
__global__ void __launch_bounds__(256, 2)
know_kernel()
{
    __shared__ float As[8][128];
    __shared__ float Bs[8][128];

    const int s = blockIdx.x;
    const int b = blockIdx.y;
    const int tid = threadIdx.x;
    const int tx = tid & 15, ty = tid >> 4;
    const int am = tid >> 1;
    const int ak = (tid & 1) << 2;

    const size_t base = (size_t)b * C * N + (size_t)am * N + (size_t)s * CHUNK + ak;
    const float* Arow = g_kg + base;
    const float* Brow = g_v  + base;

    float acc[8][8] = {};
#pragma unroll 1
    for (int kk = 0; kk < CHUNK; kk += 8) {
        float4 a4 = *(const float4*)(Arow + kk);
        As[ak + 0][am] = a4.x; As[ak + 1][am] = a4.y;
        As[ak + 2][am] = a4.z; As[ak + 3][am] = a4.w;
        float4 b4 = *(const float4*)(Brow + kk);
        Bs[ak + 0][am] = b4.x; Bs[ak + 1][am] = b4.y;
        Bs[ak + 2][am] = b4.z; Bs[ak + 3][am] = b4.w;
        __syncthreads();
        mm8(acc, As, Bs, ty, tx);
        __syncthreads();
    }

    float* dst = g_part + ((size_t)b * SPLITK + s) * C * C;
#pragma unroll
    for (int i = 0; i < 8; i++) {
        const int row = ty * 8 + i;
        *(float4*)(dst + row * C + tx * 8)     = make_float4(acc[i][0], acc[i][1], acc[i][2], acc[i][3]);
        *(float4*)(dst + row * C + tx * 8 + 4) = make_float4(acc[i][4], acc[i][5], acc[i][6], acc[i][7]);
    }
}

// ---------------------------------------------------------------------------
// Kernel 3: new_memory = mean(sig(forget)) * prev + sum(partials); write to d_out tail.
// ---------------------------------------------------------------------------
__global__ void mem_kernel(const float* __restrict__ prev, float* __restrict__ dout)
{
    const int b = blockIdx.x;
    const int tid = threadIdx.x;
    __shared__ float fs[128];
    if (tid < 128) {
        const float* p = g_fsum + ((size_t)b * C + tid) * NTILES;
        float s = 0.f;
        for (int i = 0; i < NTILES; i++) s += p[i];
        fs[tid] = s * (1.0f / (float)N);
    }
    __syncthreads();
    for (int e = tid; e < C * C; e += 256) {
        const int c = e >> 7;
        float a = fs[c] * prev[(size_t)b * C * C + e];
#pragma unroll
        for (int s2 = 0; s2 < SPLITK; s2++)
            a += g_part[((size_t)b * SPLITK + s2) * C * C + e];
        dout[OUT_ELEMS + (size_t)b * C * C + e] = a;
    }
}

// ---------------------------------------------------------------------------
// Kernel 4: E[o][c] = sum_d Wp[o][d] * M[c][d]   (one block per batch)
// ---------------------------------------------------------------------------
__global__ void __launch_bounds__(256)
e_kernel(const float* __restrict__ Wp, const float* __restrict__ dout)
{
    __shared__ float As[8][128];
    __shared__ float Bs[8][128];
    const int b = blockIdx.x;
    const float* M = dout + OUT_ELEMS + (size_t)b * C * C;
    const int tid = threadIdx.x;
    const int tx = tid & 15, ty = tid >> 4;
    const int am = tid >> 1;
    const int ak = (tid & 1) << 2;
    const float* Arow = Wp + (size_t)am * C + ak;
    const float* Brow = M  + (size_t)am * C + ak;

    float acc[8][8] = {};
#pragma unroll 1
    for (int kk = 0; kk < C; kk += 8) {
        float4 a4 = *(const float4*)(Arow + kk);
        As[ak + 0][am] = a4.x; As[ak + 1][am] = a4.y;
        As[ak + 2][am] = a4.z; As[ak + 3][am] = a4.w;
        float4 b4 = *(const float4*)(Brow + kk);
        Bs[ak + 0][am] = b4.x; Bs[ak + 1][am] = b4.y;
        Bs[ak + 2][am] = b4.z; Bs[ak + 3][am] = b4.w;
        __syncthreads();
        mm8(acc, As, Bs, ty, tx);
        __syncthreads();
    }
    float* dst = g_E + (size_t)b * C * C;
#pragma unroll
    for (int i = 0; i < 8; i++) {
        const int row = ty * 8 + i;
        *(float4*)(dst + row * C + tx * 8)     = make_float4(acc[i][0], acc[i][1], acc[i][2], acc[i][3]);
        *(float4*)(dst + row * C + tx * 8 + 4) = make_float4(acc[i][4], acc[i][5], acc[i][6], acc[i][7]);
    }
}

// ---------------------------------------------------------------------------
// Kernel 5: F = E * Wq ;  fb = E*bq + bp   (one block per batch)
// ---------------------------------------------------------------------------
__global__ void __launch_bounds__(256)
f_kernel(const float* __restrict__ Wq, const float* __restrict__ bq,
         const float* __restrict__ bp)
{
    __shared__ float As[8][128];
    __shared__ float Bs[8][128];
    const int b = blockIdx.x;
    const float* E = g_E + (size_t)b * C * C;
    const int tid = threadIdx.x;
    const int tx = tid & 15, ty = tid >> 4;
    const int am = tid >> 1;
    const int ak = (tid & 1) << 2;
    const int bkr = tid >> 5;
    const int bn  = (tid & 31) << 2;
    const float* Arow = E + (size_t)am * C + ak;

    float acc[8][8] = {};
#pragma unroll 1
    for (int kk = 0; kk < C; kk += 8) {
        float4 a4 = *(const float4*)(Arow + kk);
        As[ak + 0][am] = a4.x; As[ak + 1][am] = a4.y;
        As[ak + 2][am] = a4.z; As[ak + 3][am] = a4.w;
        *(float4*)&Bs[bkr][bn] = *(const float4*)(Wq + (size_t)(kk + bkr) * C + bn);
        __syncthreads();
        mm8(acc, As, Bs, ty, tx);
        __syncthreads();
    }
    float* dst = g_F + (size_t)b * C * C;
#pragma unroll
    for (int i = 0; i < 8; i++) {
        const int row = ty * 8 + i;
        *(float4*)(dst + row * C + tx * 8)     = make_float4(acc[i][0], acc[i][1], acc[i][2], acc[i][3]);
        *(float4*)(dst + row * C + tx * 8 + 4) = make_float4(acc[i][4], acc[i][5], acc[i][6], acc[i][7]);
    }
    __syncthreads();
    if (tid < 128) {
        float s = bp[tid];
        const float* er = E + (size_t)tid * C;
        for (int c = 0; c < C; c++) s = fmaf(er[c], bq[c], s);
        g_fb[(size_t)b * C + tid] = s;
    }
}

// ---------------------------------------------------------------------------
// Kernel 6: out[o][n] = sum_c F[o][c]*x[c][n] + fb[o] + x[o][n]
// ---------------------------------------------------------------------------
__global__ void __launch_bounds__(256, 2)
out_kernel(const float* __restrict__ x, float* __restrict__ dout)
{
    __shared__ float As[8][128];
    __shared__ float Bs[8][128];
    const int n0 = blockIdx.x << 7;
    const int b  = blockIdx.y;
    const float* F  = g_F + (size_t)b * C * C;
    const float* Xb = x + (size_t)b * C * N;

    const int tid = threadIdx.x;
    const int tx = tid & 15, ty = tid >> 4;
    const int am = tid >> 1;
    const int ak = (tid & 1) << 2;
    const int bkr = tid >> 5;
    const int bn  = (tid & 31) << 2;
    const float* Arow = F + (size_t)am * C + ak;
    const float* Brow = Xb + (size_t)bkr * N + n0 + bn;

    float acc[8][8] = {};
#pragma unroll 1
    for (int kk = 0; kk < C; kk += 8) {
        float4 a4 = *(const float4*)(Arow + kk);
        As[ak + 0][am] = a4.x; As[ak + 1][am] = a4.y;
        As[ak + 2][am] = a4.z; As[ak + 3][am] = a4.w;
        *(float4*)&Bs[bkr][bn] = *(const float4*)(Brow + (size_t)kk * N);
        __syncthreads();
        mm8(acc, As, Bs, ty, tx);
        __syncthreads();
    }

    const int ncol = n0 + tx * 8;
#pragma unroll
    for (int i = 0; i < 8; i++) {
        const int o = ty * 8 + i;
        const float fb = g_fb[(size_t)b * C + o];
        const float* xr = Xb + (size_t)o * N + ncol;
        float4 x0 = *(const float4*)(xr);
        float4 x1 = *(const float4*)(xr + 4);
        float* dst = dout + ((size_t)b * C + o) * N + ncol;
        *(float4*)(dst) = make_float4(acc[i][0] + fb + x0.x, acc[i][1] + fb + x0.y,
                                      acc[i][2] + fb + x0.z, acc[i][3] + fb + x0.w);
        *(float4*)(dst + 4) = make_float4(acc[i][4] + fb + x1.x, acc[i][5] + fb + x1.y,
                                          acc[i][6] + fb + x1.z, acc[i][7] + fb + x1.w);
    }
}

// ---------------------------------------------------------------------------
extern "C" void kernel_launch(void* const* d_in, const int* in_sizes, int n_in,
                              void* d_out, int out_size)
{
    const float* x    = (const float*)d_in[0];
    const float* prev = (const float*)d_in[1];
    const float* Wq   = (const float*)d_in[2];
    const float* bq   = (const float*)d_in[3];
    const float* Wk   = (const float*)d_in[4];
    const float* bk   = (const float*)d_in[5];
    const float* Wv   = (const float*)d_in[6];
    const float* bv   = (const float*)d_in[7];
    const float* Wg   = (const float*)d_in[8];
    const float* bg   = (const float*)d_in[9];
    const float* Wp   = (const float*)d_in[10];
    const float* bp   = (const float*)d_in[11];
    float* out = (float*)d_out;

    proj_kernel<<<dim3(N / 128, 2, BATCH * 2), 256>>>(x, Wk, bk, Wv, bv, Wg, bg);
    know_kernel<<<dim3(SPLITK, BATCH), 256>>>();
    mem_kernel<<<BATCH, 256>>>(prev, out);
    e_kernel<<<BATCH, 256>>>(Wp, out);
    f_kernel<<<BATCH, 256>>>(Wq, bq, bp);
    out_kernel<<<dim3(N / 128, BATCH), 256>>>(x, out);
}

// round 5
// speedup vs baseline: 1.0016x; 1.0016x over previous
#include <cuda_runtime.h>
#include <math.h>

static constexpr int BATCH  = 16;
static constexpr int C      = 128;
static constexpr int N      = 16384;     // H*W
static constexpr int SPLITK = 16;
static constexpr int CHUNK  = N / SPLITK;    // 1024
static constexpr int NTILES = N / 128;       // 128
static constexpr size_t OUT_ELEMS = (size_t)BATCH * C * N;   // 33,554,432

// ---------------- scratch (static device globals; no allocations) ----------
__device__ float g_kg  [(size_t)BATCH * C * N];              // k * sigmoid(input_gate)
__device__ float g_v   [(size_t)BATCH * C * N];              // v projection
__device__ float g_part[(size_t)BATCH * SPLITK * C * C];     // split-K knowledge partials
__device__ float g_fsum[(size_t)BATCH * C * NTILES];         // forget-gate partial sums
__device__ float g_E   [(size_t)BATCH * C * C];              // E = Wp * M^T
__device__ float g_F   [(size_t)BATCH * C * C];              // F = E * Wq
__device__ float g_fb  [(size_t)BATCH * C];                  // fb = E*bq + bp

__device__ __forceinline__ float sigmoidf_(float v) {
    return 1.0f / (1.0f + __expf(-v));
}

// 8x8 register-tile micro-kernel over one 8-deep smem K-slab.
__device__ __forceinline__ void mm8(float (&acc)[8][8],
                                    const float (&As)[8][128],
                                    const float (&Bs)[8][128],
                                    int ty, int tx)
{
#pragma unroll
    for (int k = 0; k < 8; k++) {
        float a_[8], b_[8];
#pragma unroll
        for (int i = 0; i < 8; i++) a_[i] = As[k][ty * 8 + i];
#pragma unroll
        for (int j = 0; j < 8; j++) b_[j] = Bs[k][tx * 8 + j];
#pragma unroll
        for (int i = 0; i < 8; i++)
#pragma unroll
            for (int j = 0; j < 8; j++)
                acc[i][j] = fmaf(a_[i], b_[j], acc[i][j]);
    }
}

// ---------------------------------------------------------------------------
// Kernel 1: fused projections.
//   type 0: rows interleave (k, input_gate) per channel -> kg = (k+bk)*sig(g2+bg2)
//   type 1: rows interleave (v, forget_gate)            -> v stored, sum sig(g1)
// Per block: 128 virtual M rows (64 channels x 2), 128 N columns, K = C = 128.
// ---------------------------------------------------------------------------
__global__ void __launch_bounds__(256, 2)
proj_kernel(const float* __restrict__ x,
            const float* __restrict__ Wk, const float* __restrict__ bk,
            const float* __restrict__ Wv, const float* __restrict__ bv,
            const float* __restrict__ Wg, const float* __restrict__ bg)
{
    __shared__ float As[8][128];
    __shared__ float Bs[8][128];
    __shared__ float red[64][16];

    const int type  = blockIdx.z & 1;
    const int b     = blockIdx.z >> 1;
    const int cbase = blockIdx.y << 6;   // 0 or 64
    const int n0    = blockIdx.x << 7;

    const float *W1, *W2, *b1, *b2;
    if (type == 0) { W1 = Wk; b1 = bk; W2 = Wg + C * C; b2 = bg + C; } // k / input gate
    else           { W1 = Wv; b1 = bv; W2 = Wg;         b2 = bg;     } // v / forget gate

    const int tid = threadIdx.x;
    const int tx = tid & 15, ty = tid >> 4;

    // A loader: virtual row am = 2*cc + p  (p=0 -> W1 row, p=1 -> W2 row)
    const int am = tid >> 1;
    const int ak = (tid & 1) << 2;
    const float* Wrow = ((am & 1) ? W2 : W1) + (size_t)(cbase + (am >> 1)) * C + ak;

    // B loader: X tile, coalesced along n
    const int bkr = tid >> 5;
    const int bn  = (tid & 31) << 2;
    const float* Xb = x + (size_t)b * C * N + (size_t)bkr * N + n0 + bn;

    float acc[8][8] = {};
#pragma unroll 1
    for (int kk = 0; kk < C; kk += 8) {
        float4 wa = *(const float4*)(Wrow + kk);
        As[ak + 0][am] = wa.x; As[ak + 1][am] = wa.y;
        As[ak + 2][am] = wa.z; As[ak + 3][am] = wa.w;
        *(float4*)&Bs[bkr][bn] = *(const float4*)(Xb + (size_t)kk * N);
        __syncthreads();
        mm8(acc, As, Bs, ty, tx);
        __syncthreads();
    }

    const int ncol = n0 + tx * 8;

    if (type == 0) {
#pragma unroll
        for (int p = 0; p < 4; p++) {
            const int c = cbase + ty * 4 + p;
            const float bb1 = b1[c], bb2 = b2[c];
            float o[8];
#pragma unroll
            for (int j = 0; j < 8; j++) {
                float kv = acc[2 * p][j]     + bb1;
                float gv = acc[2 * p + 1][j] + bb2;
                o[j] = kv * sigmoidf_(gv);
            }
            float* dst = g_kg + ((size_t)b * C + c) * N + ncol;
            *(float4*)(dst)     = make_float4(o[0], o[1], o[2], o[3]);
            *(float4*)(dst + 4) = make_float4(o[4], o[5], o[6], o[7]);
        }
    } else {
#pragma unroll
        for (int p = 0; p < 4; p++) {
            const int cc = ty * 4 + p;
            const int c  = cbase + cc;
            const float bb1 = b1[c], bb2 = b2[c];
            float o[8]; float s = 0.f;
#pragma unroll
            for (int j = 0; j < 8; j++) {
                o[j] = acc[2 * p][j] + bb1;
                s += sigmoidf_(acc[2 * p + 1][j] + bb2);
            }
            float* dst = g_v + ((size_t)b * C + c) * N + ncol;
            *(float4*)(dst)     = make_float4(o[0], o[1], o[2], o[3]);
            *(float4*)(dst + 4) = make_float4(o[4], o[5], o[6], o[7]);
            red[cc][tx] = s;
        }
        __syncthreads();
        if (tid < 64) {
            float s = 0.f;
#pragma unroll
            for (int t = 0; t < 16; t++) s += red[tid][t];
            g_fsum[((size_t)b * C + cbase + tid) * NTILES + blockIdx.x] = s;
        }
    }
}

// ---------------------------------------------------------------------------
// Kernel 2: knowledge partials.  part[b][s][c][d] = sum_{n in chunk s} kg[c,n]*v[d,n]
// ---------------------------------------------------------------------------
__global__ void __launch_bounds__(256, 2)
know_kernel()
{
    __shared__ float As[8][128];
    __shared__ float Bs[8][128];

    const int s = blockIdx.x;
    const int b = blockIdx.y;
    const int tid = threadIdx.x;
    const int tx = tid & 15, ty = tid >> 4;
    const int am = tid >> 1;
    const int ak = (tid & 1) << 2;

    const size_t base = (size_t)b * C * N + (size_t)am * N + (size_t)s * CHUNK + ak;
    const float* Arow = g_kg + base;
    const float* Brow = g_v  + base;

    float acc[8][8] = {};
#pragma unroll 1
    for (int kk = 0; kk < CHUNK; kk += 8) {
        float4 a4 = *(const float4*)(Arow + kk);
        As[ak + 0][am] = a4.x; As[ak + 1][am] = a4.y;
        As[ak + 2][am] = a4.z; As[ak + 3][am] = a4.w;
        float4 b4 = *(const float4*)(Brow + kk);
        Bs[ak + 0][am] = b4.x; Bs[ak + 1][am] = b4.y;
        Bs[ak + 2][am] = b4.z; Bs[ak + 3][am] = b4.w;
        __syncthreads();
        mm8(acc, As, Bs, ty, tx);
        __syncthreads();
    }

    float* dst = g_part + ((size_t)b * SPLITK + s) * C * C;
#pragma unroll
    for (int i = 0; i < 8; i++) {
        const int row = ty * 8 + i;
        *(float4*)(dst + row * C + tx * 8)     = make_float4(acc[i][0], acc[i][1], acc[i][2], acc[i][3]);
        *(float4*)(dst + row * C + tx * 8 + 4) = make_float4(acc[i][4], acc[i][5], acc[i][6], acc[i][7]);
    }
}

// ---------------------------------------------------------------------------
// Kernel 3: new_memory = mean(sig(forget)) * prev + sum(partials); write to d_out tail.
// ---------------------------------------------------------------------------
__global__ void mem_kernel(const float* __restrict__ prev, float* __restrict__ dout)
{
    const int b = blockIdx.x;
    const int tid = threadIdx.x;
    __shared__ float fs[128];
    if (tid < 128) {
        const float* p = g_fsum + ((size_t)b * C + tid) * NTILES;
        float s = 0.f;
        for (int i = 0; i < NTILES; i++) s += p[i];
        fs[tid] = s * (1.0f / (float)N);
    }
    __syncthreads();
    for (int e = tid; e < C * C; e += 256) {
        const int c = e >> 7;
        float a = fs[c] * prev[(size_t)b * C * C + e];
#pragma unroll
        for (int s2 = 0; s2 < SPLITK; s2++)
            a += g_part[((size_t)b * SPLITK + s2) * C * C + e];
        dout[OUT_ELEMS + (size_t)b * C * C + e] = a;
    }
}

// ---------------------------------------------------------------------------
// Kernel 4: E[o][c] = sum_d Wp[o][d] * M[c][d]   (one block per batch)
// ---------------------------------------------------------------------------
__global__ void __launch_bounds__(256)
e_kernel(const float* __restrict__ Wp, const float* __restrict__ dout)
{
    __shared__ float As[8][128];
    __shared__ float Bs[8][128];
    const int b = blockIdx.x;
    const float* M = dout + OUT_ELEMS + (size_t)b * C * C;
    const int tid = threadIdx.x;
    const int tx = tid & 15, ty = tid >> 4;
    const int am = tid >> 1;
    const int ak = (tid & 1) << 2;
    const float* Arow = Wp + (size_t)am * C + ak;
    const float* Brow = M  + (size_t)am * C + ak;

    float acc[8][8] = {};
#pragma unroll 1
    for (int kk = 0; kk < C; kk += 8) {
        float4 a4 = *(const float4*)(Arow + kk);
        As[ak + 0][am] = a4.x; As[ak + 1][am] = a4.y;
        As[ak + 2][am] = a4.z; As[ak + 3][am] = a4.w;
        float4 b4 = *(const float4*)(Brow + kk);
        Bs[ak + 0][am] = b4.x; Bs[ak + 1][am] = b4.y;
        Bs[ak + 2][am] = b4.z; Bs[ak + 3][am] = b4.w;
        __syncthreads();
        mm8(acc, As, Bs, ty, tx);
        __syncthreads();
    }
    float* dst = g_E + (size_t)b * C * C;
#pragma unroll
    for (int i = 0; i < 8; i++) {
        const int row = ty * 8 + i;
        *(float4*)(dst + row * C + tx * 8)     = make_float4(acc[i][0], acc[i][1], acc[i][2], acc[i][3]);
        *(float4*)(dst + row * C + tx * 8 + 4) = make_float4(acc[i][4], acc[i][5], acc[i][6], acc[i][7]);
    }
}

// ---------------------------------------------------------------------------
// Kernel 5: F = E * Wq ;  fb = E*bq + bp   (one block per batch)
// ---------------------------------------------------------------------------
__global__ void __launch_bounds__(256)
f_kernel(const float* __restrict__ Wq, const float* __restrict__ bq,
         const float* __restrict__ bp)
{
    __shared__ float As[8][128];
    __shared__ float Bs[8][128];
    const int b = blockIdx.x;
    const float* E = g_E + (size_t)b * C * C;
    const int tid = threadIdx.x;
    const int tx = tid & 15, ty = tid >> 4;
    const int am = tid >> 1;
    const int ak = (tid & 1) << 2;
    const int bkr = tid >> 5;
    const int bn  = (tid & 31) << 2;
    const float* Arow = E + (size_t)am * C + ak;

    float acc[8][8] = {};
#pragma unroll 1
    for (int kk = 0; kk < C; kk += 8) {
        float4 a4 = *(const float4*)(Arow + kk);
        As[ak + 0][am] = a4.x; As[ak + 1][am] = a4.y;
        As[ak + 2][am] = a4.z; As[ak + 3][am] = a4.w;
        *(float4*)&Bs[bkr][bn] = *(const float4*)(Wq + (size_t)(kk + bkr) * C + bn);
        __syncthreads();
        mm8(acc, As, Bs, ty, tx);
        __syncthreads();
    }
    float* dst = g_F + (size_t)b * C * C;
#pragma unroll
    for (int i = 0; i < 8; i++) {
        const int row = ty * 8 + i;
        *(float4*)(dst + row * C + tx * 8)     = make_float4(acc[i][0], acc[i][1], acc[i][2], acc[i][3]);
        *(float4*)(dst + row * C + tx * 8 + 4) = make_float4(acc[i][4], acc[i][5], acc[i][6], acc[i][7]);
    }
    __syncthreads();
    if (tid < 128) {
        float s = bp[tid];
        const float* er = E + (size_t)tid * C;
        for (int c = 0; c < C; c++) s = fmaf(er[c], bq[c], s);
        g_fb[(size_t)b * C + tid] = s;
    }
}

// ---------------------------------------------------------------------------
// Kernel 6: out[o][n] = sum_c F[o][c]*x[c][n] + fb[o] + x[o][n]
// ---------------------------------------------------------------------------
__global__ void __launch_bounds__(256, 2)
out_kernel(const float* __restrict__ x, float* __restrict__ dout)
{
    __shared__ float As[8][128];
    __shared__ float Bs[8][128];
    const int n0 = blockIdx.x << 7;
    const int b  = blockIdx.y;
    const float* F  = g_F + (size_t)b * C * C;
    const float* Xb = x + (size_t)b * C * N;

    const int tid = threadIdx.x;
    const int tx = tid & 15, ty = tid >> 4;
    const int am = tid >> 1;
    const int ak = (tid & 1) << 2;
    const int bkr = tid >> 5;
    const int bn  = (tid & 31) << 2;
    const float* Arow = F + (size_t)am * C + ak;
    const float* Brow = Xb + (size_t)bkr * N + n0 + bn;

    float acc[8][8] = {};
#pragma unroll 1
    for (int kk = 0; kk < C; kk += 8) {
        float4 a4 = *(const float4*)(Arow + kk);
        As[ak + 0][am] = a4.x; As[ak + 1][am] = a4.y;
        As[ak + 2][am] = a4.z; As[ak + 3][am] = a4.w;
        *(float4*)&Bs[bkr][bn] = *(const float4*)(Brow + (size_t)kk * N);
        __syncthreads();
        mm8(acc, As, Bs, ty, tx);
        __syncthreads();
    }

    const int ncol = n0 + tx * 8;
#pragma unroll
    for (int i = 0; i < 8; i++) {
        const int o = ty * 8 + i;
        const float fb = g_fb[(size_t)b * C + o];
        const float* xr = Xb + (size_t)o * N + ncol;
        float4 x0 = *(const float4*)(xr);
        float4 x1 = *(const float4*)(xr + 4);
        float* dst = dout + ((size_t)b * C + o) * N + ncol;
        *(float4*)(dst) = make_float4(acc[i][0] + fb + x0.x, acc[i][1] + fb + x0.y,
                                      acc[i][2] + fb + x0.z, acc[i][3] + fb + x0.w);
        *(float4*)(dst + 4) = make_float4(acc[i][4] + fb + x1.x, acc[i][5] + fb + x1.y,
                                          acc[i][6] + fb + x1.z, acc[i][7] + fb + x1.w);
    }
}

// ---------------------------------------------------------------------------
extern "C" void kernel_launch(void* const* d_in, const int* in_sizes, int n_in,
                              void* d_out, int out_size)
{
    const float* x    = (const float*)d_in[0];
    const float* prev = (const float*)d_in[1];
    const float* Wq   = (const float*)d_in[2];
    const float* bq   = (const float*)d_in[3];
    const float* Wk   = (const float*)d_in[4];
    const float* bk   = (const float*)d_in[5];
    const float* Wv   = (const float*)d_in[6];
    const float* bv   = (const float*)d_in[7];
    const float* Wg   = (const float*)d_in[8];
    const float* bg   = (const float*)d_in[9];
    const float* Wp   = (const float*)d_in[10];
    const float* bp   = (const float*)d_in[11];
    float* out = (float*)d_out;

    proj_kernel<<<dim3(N / 128, 2, BATCH * 2), 256>>>(x, Wk, bk, Wv, bv, Wg, bg);
    know_kernel<<<dim3(SPLITK, BATCH), 256>>>();
    mem_kernel<<<BATCH, 256>>>(prev, out);
    e_kernel<<<BATCH, 256>>>(Wp, out);
    f_kernel<<<BATCH, 256>>>(Wq, bq, bp);
    out_kernel<<<dim3(N / 128, BATCH), 256>>>(x, out);
}

// round 6
// speedup vs baseline: 1.0024x; 1.0008x over previous
#include <cuda_runtime.h>
#include <math.h>

static constexpr int BATCH  = 16;
static constexpr int C      = 128;
static constexpr int N      = 16384;     // H*W
static constexpr int SPLITK = 16;
static constexpr int CHUNK  = N / SPLITK;    // 1024
static constexpr int NTILES = N / 128;       // 128
static constexpr size_t OUT_ELEMS = (size_t)BATCH * C * N;   // 33,554,432

// ---------------- scratch (static device globals; no allocations) ----------
__device__ float g_kg  [(size_t)BATCH * C * N];              // k * sigmoid(input_gate)
__device__ float g_v   [(size_t)BATCH * C * N];              // v projection
__device__ float g_part[(size_t)BATCH * SPLITK * C * C];     // split-K knowledge partials
__device__ float g_fsum[(size_t)BATCH * C * NTILES];         // forget-gate partial sums
__device__ float g_E   [(size_t)BATCH * C * C];              // E = Wp * M^T
__device__ float g_F   [(size_t)BATCH * C * C];              // F = E * Wq
__device__ float g_fb  [(size_t)BATCH * C];                  // fb = E*bq + bp

__device__ __forceinline__ float sigmoidf_(float v) {
    return 1.0f / (1.0f + __expf(-v));
}

// 8x8 register-tile micro-kernel over one 8-deep smem K-slab.
__device__ __forceinline__ void mm8(float (&acc)[8][8],
                                    const float (&As)[8][128],
                                    const float (&Bs)[8][128],
                                    int ty, int tx)
{
#pragma unroll
    for (int k = 0; k < 8; k++) {
        float a_[8], b_[8];
#pragma unroll
        for (int i = 0; i < 8; i++) a_[i] = As[k][ty * 8 + i];
#pragma unroll
        for (int j = 0; j < 8; j++) b_[j] = Bs[k][tx * 8 + j];
#pragma unroll
        for (int i = 0; i < 8; i++)
#pragma unroll
            for (int j = 0; j < 8; j++)
                acc[i][j] = fmaf(a_[i], b_[j], acc[i][j]);
    }
}

// ---------------------------------------------------------------------------
// Kernel 1: fused projections.
//   type 0: rows interleave (k, input_gate) per channel -> kg = (k+bk)*sig(g2+bg2)
//   type 1: rows interleave (v, forget_gate)            -> v stored, sum sig(g1)
// Per block: 128 virtual M rows (64 channels x 2), 128 N columns, K = C = 128.
// ---------------------------------------------------------------------------
__global__ void __launch_bounds__(256, 2)
proj_kernel(const float* __restrict__ x,
            const float* __restrict__ Wk, const float* __restrict__ bk,
            const float* __restrict__ Wv, const float* __restrict__ bv,
            const float* __restrict__ Wg, const float* __restrict__ bg)
{
    __shared__ float As[8][128];
    __shared__ float Bs[8][128];
    __shared__ float red[64][16];

    const int type  = blockIdx.z & 1;
    const int b     = blockIdx.z >> 1;
    const int cbase = blockIdx.y << 6;   // 0 or 64
    const int n0    = blockIdx.x << 7;

    const float *W1, *W2, *b1, *b2;
    if (type == 0) { W1 = Wk; b1 = bk; W2 = Wg + C * C; b2 = bg + C; } // k / input gate
    else           { W1 = Wv; b1 = bv; W2 = Wg;         b2 = bg;     } // v / forget gate

    const int tid = threadIdx.x;
    const int tx = tid & 15, ty = tid >> 4;

    // A loader: virtual row am = 2*cc + p  (p=0 -> W1 row, p=1 -> W2 row)
    const int am = tid >> 1;
    const int ak = (tid & 1) << 2;
    const float* Wrow = ((am & 1) ? W2 : W1) + (size_t)(cbase + (am >> 1)) * C + ak;

    // B loader: X tile, coalesced along n
    const int bkr = tid >> 5;
    const int bn  = (tid & 31) << 2;
    const float* Xb = x + (size_t)b * C * N + (size_t)bkr * N + n0 + bn;

    float acc[8][8] = {};
#pragma unroll 1
    for (int kk = 0; kk < C; kk += 8) {
        float4 wa = *(const float4*)(Wrow + kk);
        As[ak + 0][am] = wa.x; As[ak + 1][am] = wa.y;
        As[ak + 2][am] = wa.z; As[ak + 3][am] = wa.w;
        *(float4*)&Bs[bkr][bn] = *(const float4*)(Xb + (size_t)kk * N);
        __syncthreads();
        mm8(acc, As, Bs, ty, tx);
        __syncthreads();
    }

    const int ncol = n0 + tx * 8;

    if (type == 0) {
#pragma unroll
        for (int p = 0; p < 4; p++) {
            const int c = cbase + ty * 4 + p;
            const float bb1 = b1[c], bb2 = b2[c];
            float o[8];
#pragma unroll
            for (int j = 0; j < 8; j++) {
                float kv = acc[2 * p][j]     + bb1;
                float gv = acc[2 * p + 1][j] + bb2;
                o[j] = kv * sigmoidf_(gv);
            }
            float* dst = g_kg + ((size_t)b * C + c) * N + ncol;
            *(float4*)(dst)     = make_float4(o[0], o[1], o[2], o[3]);
            *(float4*)(dst + 4) = make_float4(o[4], o[5], o[6], o[7]);
        }
    } else {
#pragma unroll
        for (int p = 0; p < 4; p++) {
            const int cc = ty * 4 + p;
            const int c  = cbase + cc;
            const float bb1 = b1[c], bb2 = b2[c];
            float o[8]; float s = 0.f;
#pragma unroll
            for (int j = 0; j < 8; j++) {
                o[j] = acc[2 * p][j] + bb1;
                s += sigmoidf_(acc[2 * p + 1][j] + bb2);
            }
            float* dst = g_v + ((size_t)b * C + c) * N + ncol;
            *(float4*)(dst)     = make_float4(o[0], o[1], o[2], o[3]);
            *(float4*)(dst + 4) = make_float4(o[4], o[5], o[6], o[7]);
            red[cc][tx] = s;
        }
        __syncthreads();
        if (tid < 64) {
            float s = 0.f;
#pragma unroll
            for (int t = 0; t < 16; t++) s += red[tid][t];
            g_fsum[((size_t)b * C + cbase + tid) * NTILES + blockIdx.x] = s;
        }
    }
}

// ---------------------------------------------------------------------------
// Kernel 2: knowledge partials.  part[b][s][c][d] = sum_{n in chunk s} kg[c,n]*v[d,n]
// ---------------------------------------------------------------------------
__global__ void __launch_bounds__(256, 2)
know_kernel()
{
    __shared__ float As[8][128];
    __shared__ float Bs[8][128];

    const int s = blockIdx.x;
    const int b = blockIdx.y;
    const int tid = threadIdx.x;
    const int tx = tid & 15, ty = tid >> 4;
    const int am = tid >> 1;
    const int ak = (tid & 1) << 2;

    const size_t base = (size_t)b * C * N + (size_t)am * N + (size_t)s * CHUNK + ak;
    const float* Arow = g_kg + base;
    const float* Brow = g_v  + base;

    float acc[8][8] = {};
#pragma unroll 1
    for (int kk = 0; kk < CHUNK; kk += 8) {
        float4 a4 = *(const float4*)(Arow + kk);
        As[ak + 0][am] = a4.x; As[ak + 1][am] = a4.y;
        As[ak + 2][am] = a4.z; As[ak + 3][am] = a4.w;
        float4 b4 = *(const float4*)(Brow + kk);
        Bs[ak + 0][am] = b4.x; Bs[ak + 1][am] = b4.y;
        Bs[ak + 2][am] = b4.z; Bs[ak + 3][am] = b4.w;
        __syncthreads();
        mm8(acc, As, Bs, ty, tx);
        __syncthreads();
    }

    float* dst = g_part + ((size_t)b * SPLITK + s) * C * C;
#pragma unroll
    for (int i = 0; i < 8; i++) {
        const int row = ty * 8 + i;
        *(float4*)(dst + row * C + tx * 8)     = make_float4(acc[i][0], acc[i][1], acc[i][2], acc[i][3]);
        *(float4*)(dst + row * C + tx * 8 + 4) = make_float4(acc[i][4], acc[i][5], acc[i][6], acc[i][7]);
    }
}

// ---------------------------------------------------------------------------
// Kernel 3: new_memory = mean(sig(forget)) * prev + sum(partials); write to d_out tail.
// ---------------------------------------------------------------------------
__global__ void mem_kernel(const float* __restrict__ prev, float* __restrict__ dout)
{
    const int b = blockIdx.x;
    const int tid = threadIdx.x;
    __shared__ float fs[128];
    if (tid < 128) {
        const float* p = g_fsum + ((size_t)b * C + tid) * NTILES;
        float s = 0.f;
        for (int i = 0; i < NTILES; i++) s += p[i];
        fs[tid] = s * (1.0f / (float)N);
    }
    __syncthreads();
    for (int e = tid; e < C * C; e += 256) {
        const int c = e >> 7;
        float a = fs[c] * prev[(size_t)b * C * C + e];
#pragma unroll
        for (int s2 = 0; s2 < SPLITK; s2++)
            a += g_part[((size_t)b * SPLITK + s2) * C * C + e];
        dout[OUT_ELEMS + (size_t)b * C * C + e] = a;
    }
}

// ---------------------------------------------------------------------------
// Kernel 4: E[o][c] = sum_d Wp[o][d] * M[c][d]   (one block per batch)
// ---------------------------------------------------------------------------
__global__ void __launch_bounds__(256)
e_kernel(const float* __restrict__ Wp, const float* __restrict__ dout)
{
    __shared__ float As[8][128];
    __shared__ float Bs[8][128];
    const int b = blockIdx.x;
    const float* M = dout + OUT_ELEMS + (size_t)b * C * C;
    const int tid = threadIdx.x;
    const int tx = tid & 15, ty = tid >> 4;
    const int am = tid >> 1;
    const int ak = (tid & 1) << 2;
    const float* Arow = Wp + (size_t)am * C + ak;
    const float* Brow = M  + (size_t)am * C + ak;

    float acc[8][8] = {};
#pragma unroll 1
    for (int kk = 0; kk < C; kk += 8) {
        float4 a4 = *(const float4*)(Arow + kk);
        As[ak + 0][am] = a4.x; As[ak + 1][am] = a4.y;
        As[ak + 2][am] = a4.z; As[ak + 3][am] = a4.w;
        float4 b4 = *(const float4*)(Brow + kk);
        Bs[ak + 0][am] = b4.x; Bs[ak + 1][am] = b4.y;
        Bs[ak + 2][am] = b4.z; Bs[ak + 3][am] = b4.w;
        __syncthreads();
        mm8(acc, As, Bs, ty, tx);
        __syncthreads();
    }
    float* dst = g_E + (size_t)b * C * C;
#pragma unroll
    for (int i = 0; i < 8; i++) {
        const int row = ty * 8 + i;
        *(float4*)(dst + row * C + tx * 8)     = make_float4(acc[i][0], acc[i][1], acc[i][2], acc[i][3]);
        *(float4*)(dst + row * C + tx * 8 + 4) = make_float4(acc[i][4], acc[i][5], acc[i][6], acc[i][7]);
    }
}

// ---------------------------------------------------------------------------
// Kernel 5: F = E * Wq ;  fb = E*bq + bp   (one block per batch)
// ---------------------------------------------------------------------------
__global__ void __launch_bounds__(256)
f_kernel(const float* __restrict__ Wq, const float* __restrict__ bq,
         const float* __restrict__ bp)
{
    __shared__ float As[8][128];
    __shared__ float Bs[8][128];
    const int b = blockIdx.x;
    const float* E = g_E + (size_t)b * C * C;
    const int tid = threadIdx.x;
    const int tx = tid & 15, ty = tid >> 4;
    const int am = tid >> 1;
    const int ak = (tid & 1) << 2;
    const int bkr = tid >> 5;
    const int bn  = (tid & 31) << 2;
    const float* Arow = E + (size_t)am * C + ak;

    float acc[8][8] = {};
#pragma unroll 1
    for (int kk = 0; kk < C; kk += 8) {
        float4 a4 = *(const float4*)(Arow + kk);
        As[ak + 0][am] = a4.x; As[ak + 1][am] = a4.y;
        As[ak + 2][am] = a4.z; As[ak + 3][am] = a4.w;
        *(float4*)&Bs[bkr][bn] = *(const float4*)(Wq + (size_t)(kk + bkr) * C + bn);
        __syncthreads();
        mm8(acc, As, Bs, ty, tx);
        __syncthreads();
    }
    float* dst = g_F + (size_t)b * C * C;
#pragma unroll
    for (int i = 0; i < 8; i++) {
        const int row = ty * 8 + i;
        *(float4*)(dst + row * C + tx * 8)     = make_float4(acc[i][0], acc[i][1], acc[i][2], acc[i][3]);
        *(float4*)(dst + row * C + tx * 8 + 4) = make_float4(acc[i][4], acc[i][5], acc[i][6], acc[i][7]);
    }
    __syncthreads();
    if (tid < 128) {
        float s = bp[tid];
        const float* er = E + (size_t)tid * C;
        for (int c = 0; c < C; c++) s = fmaf(er[c], bq[c], s);
        g_fb[(size_t)b * C + tid] = s;
    }
}

// ---------------------------------------------------------------------------
// Kernel 6: out[o][n] = sum_c F[o][c]*x[c][n] + fb[o] + x[o][n]
// ---------------------------------------------------------------------------
__global__ void __launch_bounds__(256, 2)
out_kernel(const float* __restrict__ x, float* __restrict__ dout)
{
    __shared__ float As[8][128];
    __shared__ float Bs[8][128];
    const int n0 = blockIdx.x << 7;
    const int b  = blockIdx.y;
    const float* F  = g_F + (size_t)b * C * C;
    const float* Xb = x + (size_t)b * C * N;

    const int tid = threadIdx.x;
    const int tx = tid & 15, ty = tid >> 4;
    const int am = tid >> 1;
    const int ak = (tid & 1) << 2;
    const int bkr = tid >> 5;
    const int bn  = (tid & 31) << 2;
    const float* Arow = F + (size_t)am * C + ak;
    const float* Brow = Xb + (size_t)bkr * N + n0 + bn;

    float acc[8][8] = {};
#pragma unroll 1
    for (int kk = 0; kk < C; kk += 8) {
        float4 a4 = *(const float4*)(Arow + kk);
        As[ak + 0][am] = a4.x; As[ak + 1][am] = a4.y;
        As[ak + 2][am] = a4.z; As[ak + 3][am] = a4.w;
        *(float4*)&Bs[bkr][bn] = *(const float4*)(Brow + (size_t)kk * N);
        __syncthreads();
        mm8(acc, As, Bs, ty, tx);
        __syncthreads();
    }

    const int ncol = n0 + tx * 8;
#pragma unroll
    for (int i = 0; i < 8; i++) {
        const int o = ty * 8 + i;
        const float fb = g_fb[(size_t)b * C + o];
        const float* xr = Xb + (size_t)o * N + ncol;
        float4 x0 = *(const float4*)(xr);
        float4 x1 = *(const float4*)(xr + 4);
        float* dst = dout + ((size_t)b * C + o) * N + ncol;
        *(float4*)(dst) = make_float4(acc[i][0] + fb + x0.x, acc[i][1] + fb + x0.y,
                                      acc[i][2] + fb + x0.z, acc[i][3] + fb + x0.w);
        *(float4*)(dst + 4) = make_float4(acc[i][4] + fb + x1.x, acc[i][5] + fb + x1.y,
                                          acc[i][6] + fb + x1.z, acc[i][7] + fb + x1.w);
    }
}

// ---------------------------------------------------------------------------
extern "C" void kernel_launch(void* const* d_in, const int* in_sizes, int n_in,
                              void* d_out, int out_size)
{
    const float* x    = (const float*)d_in[0];
    const float* prev = (const float*)d_in[1];
    const float* Wq   = (const float*)d_in[2];
    const float* bq   = (const float*)d_in[3];
    const float* Wk   = (const float*)d_in[4];
    const float* bk   = (const float*)d_in[5];
    const float* Wv   = (const float*)d_in[6];
    const float* bv   = (const float*)d_in[7];
    const float* Wg   = (const float*)d_in[8];
    const float* bg   = (const float*)d_in[9];
    const float* Wp   = (const float*)d_in[10];
    const float* bp   = (const float*)d_in[11];
    float* out = (float*)d_out;

    proj_kernel<<<dim3(N / 128, 2, BATCH * 2), 256>>>(x, Wk, bk, Wv, bv, Wg, bg);
    know_kernel<<<dim3(SPLITK, BATCH), 256>>>();
    mem_kernel<<<BATCH, 256>>>(prev, out);
    e_kernel<<<BATCH, 256>>>(Wp, out);
    f_kernel<<<BATCH, 256>>>(Wq, bq, bp);
    out_kernel<<<dim3(N / 128, BATCH), 256>>>(x, out);
}

// round 7
// speedup vs baseline: 2.0615x; 2.0566x over previous
#include <cuda_runtime.h>
#include <stdint.h>
#include <math.h>

static constexpr int BATCH  = 16;
static constexpr int C      = 128;
static constexpr int N      = 16384;
static constexpr int SPLITK = 16;
static constexpr int CHUNK  = N / SPLITK;    // 1024
static constexpr int NTILES = N / 128;       // 128
static constexpr size_t OUT_ELEMS = (size_t)BATCH * C * N;
static constexpr int LDS_ = 136;             // padded smem stride (words): bank = (8k+m)%32, conflict-free frags

// ---------------- scratch (static device globals; no allocations) ----------
__device__ float g_kg  [(size_t)BATCH * C * N];
__device__ float g_v   [(size_t)BATCH * C * N];
__device__ float g_part[(size_t)BATCH * SPLITK * C * C];
__device__ float g_fsum[(size_t)BATCH * C * NTILES];
__device__ float g_E   [(size_t)BATCH * C * C];
__device__ float g_F   [(size_t)BATCH * C * C];
__device__ float g_fb  [(size_t)BATCH * C];

__device__ __forceinline__ float sigmoidf_(float v) { return 1.0f / (1.0f + __expf(-v)); }

__device__ __forceinline__ uint32_t f2tf(float f) {
    uint32_t u; asm("cvt.rna.tf32.f32 %0, %1;" : "=r"(u) : "f"(f)); return u;
}

__device__ __forceinline__ void mma_tf32(float c[4],
    uint32_t a0, uint32_t a1, uint32_t a2, uint32_t a3, uint32_t b0, uint32_t b1)
{
    asm volatile(
        "mma.sync.aligned.m16n8k8.row.col.f32.tf32.tf32.f32 "
        "{%0,%1,%2,%3}, {%4,%5,%6,%7}, {%8,%9}, {%0,%1,%2,%3};\n"
        : "+f"(c[0]), "+f"(c[1]), "+f"(c[2]), "+f"(c[3])
        : "r"(a0), "r"(a1), "r"(a2), "r"(a3), "r"(b0), "r"(b1));
}

// Transpose loader: S[k][m] = myrow[kbase + k], thread owns fixed m = tid>>1, koff = (tid&1)*8.
__device__ __forceinline__ void load_transpose(uint32_t (*S)[LDS_], const float* myrow,
                                               int kbase, int tid)
{
    const int m = tid >> 1, koff = (tid & 1) << 3;
    const float* p = myrow + kbase + koff;
    float4 u = *(const float4*)p;
    float4 v = *(const float4*)(p + 4);
    S[koff + 0][m] = f2tf(u.x); S[koff + 1][m] = f2tf(u.y);
    S[koff + 2][m] = f2tf(u.z); S[koff + 3][m] = f2tf(u.w);
    S[koff + 4][m] = f2tf(v.x); S[koff + 5][m] = f2tf(v.y);
    S[koff + 6][m] = f2tf(v.z); S[koff + 7][m] = f2tf(v.w);
}

// Direct loader: S[k][n] = src[(kbase+k)*ld + n0 + n]
__device__ __forceinline__ void load_direct(uint32_t (*S)[LDS_], const float* src,
                                            size_t ld, int n0, int kbase, int tid)
{
    const int kb = tid >> 4, nb = (tid & 15) << 3;
    const float* p = src + (size_t)(kbase + kb) * ld + n0 + nb;
    float4 u = *(const float4*)p;
    float4 v = *(const float4*)(p + 4);
    *(uint4*)&S[kb][nb]     = make_uint4(f2tf(u.x), f2tf(u.y), f2tf(u.z), f2tf(u.w));
    *(uint4*)&S[kb][nb + 4] = make_uint4(f2tf(v.x), f2tf(v.y), f2tf(v.z), f2tf(v.w));
}

// One 16-deep K-slab of the 128x128 block tile. Warp tile 64x32 (4 mfrag x 4 nfrag).
// Fragment maps (PTX m16n8k8 tf32): a0(g,tig) a1(g+8,tig) a2(g,tig+4) a3(g+8,tig+4);
// b0(tig,g) b1(tig+4,g); c0(g,2tig) c1(g,2tig+1) c2(g+8,2tig) c3(g+8,2tig+1).
__device__ __forceinline__ void compute_slab(const uint32_t (*As)[LDS_], const uint32_t (*Bs)[LDS_],
                                             float acc[4][4][4], int mrow, int ncol, int g, int tig)
{
#pragma unroll
    for (int ks = 0; ks < 2; ks++) {
        uint32_t a[4][4], b[4][2];
#pragma unroll
        for (int mf = 0; mf < 4; mf++) {
            const int m = mrow + mf * 16 + g;
            a[mf][0] = As[ks * 8 + tig][m];
            a[mf][1] = As[ks * 8 + tig][m + 8];
            a[mf][2] = As[ks * 8 + tig + 4][m];
            a[mf][3] = As[ks * 8 + tig + 4][m + 8];
        }
#pragma unroll
        for (int nf = 0; nf < 4; nf++) {
            const int n = ncol + nf * 8 + g;
            b[nf][0] = Bs[ks * 8 + tig][n];
            b[nf][1] = Bs[ks * 8 + tig + 4][n];
        }
#pragma unroll
        for (int mf = 0; mf < 4; mf++)
#pragma unroll
            for (int nf = 0; nf < 4; nf++)
                mma_tf32(acc[mf][nf], a[mf][0], a[mf][1], a[mf][2], a[mf][3],
                         b[nf][0], b[nf][1]);
    }
}

// ---------------------------------------------------------------------------
// Kernel 1: fused projections (tensor cores).
// M rows of the tile: each 16-row group holds 8 channels' value rows (0-7)
// and the SAME channels' gate rows (8-15) -> value+gate pair lives in one thread.
// blockIdx.x: 0..3 -> type=x>>1 (0: k/input_gate, 1: v/forget_gate), half=x&1.
// ---------------------------------------------------------------------------
__global__ void __launch_bounds__(256, 2)
proj_tc(const float* __restrict__ x,
        const float* __restrict__ Wk, const float* __restrict__ bk,
        const float* __restrict__ Wv, const float* __restrict__ bv,
        const float* __restrict__ Wg, const float* __restrict__ bg)
{
    __shared__ uint32_t As[16][LDS_];
    __shared__ uint32_t Bs[16][LDS_];
    __shared__ float red[64][4];

    const int idx   = blockIdx.x;
    const int type  = idx >> 1;
    const int cbase = (idx & 1) * 64;
    const int n0    = blockIdx.y << 7;
    const int b     = blockIdx.z;

    const float *W1, *W2, *b1, *b2;
    if (type == 0) { W1 = Wk; b1 = bk; W2 = Wg + C * C; b2 = bg + C; }
    else           { W1 = Wv; b1 = bv; W2 = Wg;         b2 = bg;     }

    const int tid = threadIdx.x, lane = tid & 31, warp = tid >> 5;
    const int g = lane >> 2, tig = lane & 3;
    const int warpM = warp & 1, warpN = warp >> 1;
    const int mrow = warpM * 64, ncol = warpN * 32;

    // Per-thread A source row (fixed): m -> (channel, W1|W2)
    const int am = tid >> 1;
    const int agrp = am >> 4, awi = am & 15;
    const int ach = cbase + agrp * 8 + (awi & 7);
    const float* myArow = ((awi < 8) ? W1 : W2) + (size_t)ach * C;

    const float* xb = x + (size_t)b * C * N;

    float acc[4][4][4] = {};
#pragma unroll 1
    for (int kk = 0; kk < C; kk += 16) {
        load_transpose(As, myArow, kk, tid);
        load_direct(Bs, xb, N, n0, kk, tid);
        __syncthreads();
        compute_slab(As, Bs, acc, mrow, ncol, g, tig);
        __syncthreads();
    }

    if (type == 0) {
#pragma unroll
        for (int mf = 0; mf < 4; mf++) {
            const int ch = cbase + (warpM * 4 + mf) * 8 + g;
            const float bb1 = b1[ch], bb2 = b2[ch];
            float* dst = g_kg + ((size_t)b * C + ch) * N + n0 + ncol + 2 * tig;
#pragma unroll
            for (int nf = 0; nf < 4; nf++) {
                float o0 = (acc[mf][nf][0] + bb1) * sigmoidf_(acc[mf][nf][2] + bb2);
                float o1 = (acc[mf][nf][1] + bb1) * sigmoidf_(acc[mf][nf][3] + bb2);
                *(float2*)(dst + nf * 8) = make_float2(o0, o1);
            }
        }
    } else {
#pragma unroll
        for (int mf = 0; mf < 4; mf++) {
            const int ch = cbase + (warpM * 4 + mf) * 8 + g;
            const float bb1 = b1[ch], bb2 = b2[ch];
            float* dv = g_v + ((size_t)b * C + ch) * N + n0 + ncol + 2 * tig;
            float s = 0.f;
#pragma unroll
            for (int nf = 0; nf < 4; nf++) {
                *(float2*)(dv + nf * 8) = make_float2(acc[mf][nf][0] + bb1,
                                                      acc[mf][nf][1] + bb1);
                s += sigmoidf_(acc[mf][nf][2] + bb2) + sigmoidf_(acc[mf][nf][3] + bb2);
            }
            s += __shfl_xor_sync(0xffffffffu, s, 1);
            s += __shfl_xor_sync(0xffffffffu, s, 2);
            if (tig == 0) red[warpM * 32 + mf * 8 + g][warpN] = s;
        }
        __syncthreads();
        if (tid < 64) {
            float s = red[tid][0] + red[tid][1] + red[tid][2] + red[tid][3];
            g_fsum[((size_t)b * C + cbase + tid) * NTILES + blockIdx.y] = s;
        }
    }
}

// ---------------------------------------------------------------------------
// Kernel 2: knowledge partials (NT GEMM, both operands K-fast -> two transpose loads)
// ---------------------------------------------------------------------------
__global__ void __launch_bounds__(256, 2)
know_tc()
{
    __shared__ uint32_t As[16][LDS_];
    __shared__ uint32_t Bs[16][LDS_];

    const int s = blockIdx.x, b = blockIdx.y;
    const int tid = threadIdx.x, lane = tid & 31, warp = tid >> 5;
    const int g = lane >> 2, tig = lane & 3;
    const int warpM = warp & 1, warpN = warp >> 1;
    const int mrow = warpM * 64, ncol = warpN * 32;

    const int am = tid >> 1;
    const float* arow = g_kg + ((size_t)b * C + am) * N + (size_t)s * CHUNK;
    const float* brow = g_v  + ((size_t)b * C + am) * N + (size_t)s * CHUNK;

    float acc[4][4][4] = {};
#pragma unroll 1
    for (int kk = 0; kk < CHUNK; kk += 16) {
        load_transpose(As, arow, kk, tid);
        load_transpose(Bs, brow, kk, tid);
        __syncthreads();
        compute_slab(As, Bs, acc, mrow, ncol, g, tig);
        __syncthreads();
    }

    float* dst = g_part + ((size_t)b * SPLITK + s) * C * C;
#pragma unroll
    for (int mf = 0; mf < 4; mf++) {
        const int row = mrow + mf * 16 + g;
#pragma unroll
        for (int nf = 0; nf < 4; nf++) {
            const int col = ncol + nf * 8 + 2 * tig;
            *(float2*)(dst + (size_t)row * C + col)       = make_float2(acc[mf][nf][0], acc[mf][nf][1]);
            *(float2*)(dst + (size_t)(row + 8) * C + col) = make_float2(acc[mf][nf][2], acc[mf][nf][3]);
        }
    }
}

// ---------------------------------------------------------------------------
// Kernel 3: new_memory = mean(sig(forget)) * prev + sum(partials); -> d_out tail (fp32)
// ---------------------------------------------------------------------------
__global__ void mem_kernel(const float* __restrict__ prev, float* __restrict__ dout)
{
    const int b = blockIdx.x;
    const int tid = threadIdx.x;
    __shared__ float fs[128];
    if (tid < 128) {
        const float* p = g_fsum + ((size_t)b * C + tid) * NTILES;
        float s = 0.f;
        for (int i = 0; i < NTILES; i++) s += p[i];
        fs[tid] = s * (1.0f / (float)N);
    }
    __syncthreads();
    for (int e = tid; e < C * C; e += 256) {
        const int c = e >> 7;
        float a = fs[c] * prev[(size_t)b * C * C + e];
#pragma unroll
        for (int s2 = 0; s2 < SPLITK; s2++)
            a += g_part[((size_t)b * SPLITK + s2) * C * C + e];
        dout[OUT_ELEMS + (size_t)b * C * C + e] = a;
    }
}

// ---------------------------------------------------------------------------
// Kernel 4: E = Wp * M^T  (tensor cores, one block per batch, K=128)
// ---------------------------------------------------------------------------
__global__ void __launch_bounds__(256, 2)
e_tc(const float* __restrict__ Wp, const float* __restrict__ dout)
{
    __shared__ uint32_t As[16][LDS_];
    __shared__ uint32_t Bs[16][LDS_];
    const int b = blockIdx.x;
    const float* M = dout + OUT_ELEMS + (size_t)b * C * C;

    const int tid = threadIdx.x, lane = tid & 31, warp = tid >> 5;
    const int g = lane >> 2, tig = lane & 3;
    const int warpM = warp & 1, warpN = warp >> 1;
    const int mrow = warpM * 64, ncol = warpN * 32;

    const int am = tid >> 1;
    const float* arow = Wp + (size_t)am * C;   // As[k=d][o] = Wp[o][d]
    const float* brow = M  + (size_t)am * C;   // Bs[k=d][c] = M[c][d]

    float acc[4][4][4] = {};
#pragma unroll 1
    for (int kk = 0; kk < C; kk += 16) {
        load_transpose(As, arow, kk, tid);
        load_transpose(Bs, brow, kk, tid);
        __syncthreads();
        compute_slab(As, Bs, acc, mrow, ncol, g, tig);
        __syncthreads();
    }

    float* dst = g_E + (size_t)b * C * C;
#pragma unroll
    for (int mf = 0; mf < 4; mf++) {
        const int row = mrow + mf * 16 + g;
#pragma unroll
        for (int nf = 0; nf < 4; nf++) {
            const int col = ncol + nf * 8 + 2 * tig;
            *(float2*)(dst + (size_t)row * C + col)       = make_float2(acc[mf][nf][0], acc[mf][nf][1]);
            *(float2*)(dst + (size_t)(row + 8) * C + col) = make_float2(acc[mf][nf][2], acc[mf][nf][3]);
        }
    }
}

// ---------------------------------------------------------------------------
// Kernel 5: F = E * Wq ; fb = E*bq + bp
// ---------------------------------------------------------------------------
__global__ void __launch_bounds__(256, 2)
f_tc(const float* __restrict__ Wq, const float* __restrict__ bq,
     const float* __restrict__ bp)
{
    __shared__ uint32_t As[16][LDS_];
    __shared__ uint32_t Bs[16][LDS_];
    const int b = blockIdx.x;
    const float* E = g_E + (size_t)b * C * C;

    const int tid = threadIdx.x, lane = tid & 31, warp = tid >> 5;
    const int g = lane >> 2, tig = lane & 3;
    const int warpM = warp & 1, warpN = warp >> 1;
    const int mrow = warpM * 64, ncol = warpN * 32;

    const int am = tid >> 1;
    const float* arow = E + (size_t)am * C;    // As[k=c][o] = E[o][c]

    float acc[4][4][4] = {};
#pragma unroll 1
    for (int kk = 0; kk < C; kk += 16) {
        load_transpose(As, arow, kk, tid);
        load_direct(Bs, Wq, C, 0, kk, tid);    // Bs[k=c][j] = Wq[c][j]
        __syncthreads();
        compute_slab(As, Bs, acc, mrow, ncol, g, tig);
        __syncthreads();
    }

    float* dst = g_F + (size_t)b * C * C;
#pragma unroll
    for (int mf = 0; mf < 4; mf++) {
        const int row = mrow + mf * 16 + g;
#pragma unroll
        for (int nf = 0; nf < 4; nf++) {
            const int col = ncol + nf * 8 + 2 * tig;
            *(float2*)(dst + (size_t)row * C + col)       = make_float2(acc[mf][nf][0], acc[mf][nf][1]);
            *(float2*)(dst + (size_t)(row + 8) * C + col) = make_float2(acc[mf][nf][2], acc[mf][nf][3]);
        }
    }
    __syncthreads();
    if (tid < 128) {
        float s = bp[tid];
        const float* er = E + (size_t)tid * C;
        for (int c = 0; c < C; c++) s = fmaf(er[c], bq[c], s);
        g_fb[(size_t)b * C + tid] = s;
    }
}

// ---------------------------------------------------------------------------
// Kernel 6: out = F*x + fb + x  (tensor cores + residual epilogue)
// ---------------------------------------------------------------------------
__global__ void __launch_bounds__(256, 2)
out_tc(const float* __restrict__ x, float* __restrict__ dout)
{
    __shared__ uint32_t As[16][LDS_];
    __shared__ uint32_t Bs[16][LDS_];
    const int n0 = blockIdx.x << 7;
    const int b  = blockIdx.y;
    const float* xb = x + (size_t)b * C * N;

    const int tid = threadIdx.x, lane = tid & 31, warp = tid >> 5;
    const int g = lane >> 2, tig = lane & 3;
    const int warpM = warp & 1, warpN = warp >> 1;
    const int mrow = warpM * 64, ncol = warpN * 32;

    const int am = tid >> 1;
    const float* arow = g_F + (size_t)b * C * C + (size_t)am * C;  // As[k=c][o] = F[o][c]

    float acc[4][4][4] = {};
#pragma unroll 1
    for (int kk = 0; kk < C; kk += 16) {
        load_transpose(As, arow, kk, tid);
        load_direct(Bs, xb, N, n0, kk, tid);
        __syncthreads();
        compute_slab(As, Bs, acc, mrow, ncol, g, tig);
        __syncthreads();
    }

#pragma unroll
    for (int mf = 0; mf < 4; mf++) {
        const int o = mrow + mf * 16 + g;
        const float fb0 = g_fb[(size_t)b * C + o];
        const float fb1 = g_fb[(size_t)b * C + o + 8];
#pragma unroll
        for (int nf = 0; nf < 4; nf++) {
            const int col = n0 + ncol + nf * 8 + 2 * tig;
            float2 r0 = *(const float2*)(xb + (size_t)o * N + col);
            float2 r1 = *(const float2*)(xb + (size_t)(o + 8) * N + col);
            *(float2*)(dout + ((size_t)b * C + o) * N + col) =
                make_float2(acc[mf][nf][0] + fb0 + r0.x, acc[mf][nf][1] + fb0 + r0.y);
            *(float2*)(dout + ((size_t)b * C + o + 8) * N + col) =
                make_float2(acc[mf][nf][2] + fb1 + r1.x, acc[mf][nf][3] + fb1 + r1.y);
        }
    }
}

// ---------------------------------------------------------------------------
extern "C" void kernel_launch(void* const* d_in, const int* in_sizes, int n_in,
                              void* d_out, int out_size)
{
    const float* x    = (const float*)d_in[0];
    const float* prev = (const float*)d_in[1];
    const float* Wq   = (const float*)d_in[2];
    const float* bq   = (const float*)d_in[3];
    const float* Wk   = (const float*)d_in[4];
    const float* bk   = (const float*)d_in[5];
    const float* Wv   = (const float*)d_in[6];
    const float* bv   = (const float*)d_in[7];
    const float* Wg   = (const float*)d_in[8];
    const float* bg   = (const float*)d_in[9];
    const float* Wp   = (const float*)d_in[10];
    const float* bp   = (const float*)d_in[11];
    float* out = (float*)d_out;

    proj_tc<<<dim3(4, NTILES, BATCH), 256>>>(x, Wk, bk, Wv, bv, Wg, bg);
    know_tc<<<dim3(SPLITK, BATCH), 256>>>();
    mem_kernel<<<BATCH, 256>>>(prev, out);
    e_tc<<<BATCH, 256>>>(Wp, out);
    f_tc<<<BATCH, 256>>>(Wq, bq, bp);
    out_tc<<<dim3(NTILES, BATCH), 256>>>(x, out);
}